// round 12
// baseline (speedup 1.0000x reference)
#include <cuda_runtime.h>
#include <math.h>

#define BN 4
#define CC 60
#define NA 25
#define HW 9216
#define HW2 2304
#define DN 1500
#define NHW 230400   // NA*HW
#define TD 180

// ---------------- scratch: __device__ globals (allocation-free) ----------------
static __device__ __align__(16) float g_sqT [(size_t)BN*DN*HW];    // (b, dn, hw)  Q^T, K-major for GEMM1
static __device__ __align__(16) float g_skv [(size_t)BN*3000*HW2]; // (b, 3000, hw2): rows 0..1499 = K (dn), 1500..2999 = V (dn)
static __device__ __align__(16) float g_S   [(size_t)BN*HW*HW2];   // scores / probs
static __device__ __align__(16) float g_aqkv[(size_t)BN*TD*NHW];   // (b, 180, n, hw)
static __device__ __align__(16) float g_fqkv[(size_t)BN*TD*NHW];   // (b, 180, n*hw)
static __device__ __align__(16) float g_cat [(size_t)BN*4500*HW];  // (b, 180*25, hw) concat features
static __device__ float g_rq[BN*HW];
static __device__ float g_rk[BN*HW2];
static __device__ float g_aqn[BN*NA], g_akn[BN*NA];
static __device__ float g_fqn[BN*CC], g_fkn[BN*CC];
static __device__ float g_Ga[BN*NA*NA], g_Aatt[BN*NA*NA];
static __device__ float g_Gf[BN*CC*CC], g_Fatt[BN*CC*CC];

// ---------------- zero Gram accumulators ----------------
__global__ void k_zero() {
    int i = blockIdx.x*256 + threadIdx.x;
    if (i < BN*NA*NA) g_Ga[i] = 0.f;
    if (i < BN*CC*CC) g_Gf[i] = 0.f;
}

// ---------------- spatial Q projection: g_sqT[b][dd*25+nn][hw] ----------------
__global__ __launch_bounds__(256) void k_proj_sq(const float* __restrict__ x,
                                                 const float* __restrict__ w) {
    __shared__ float Ws[CC*CC];
    int tid = threadIdx.x;
    for (int i = tid; i < CC*CC; i += 256) Ws[i] = w[i];
    __syncthreads();
    int bn = blockIdx.y, b = bn/NA, nn = bn%NA;
    int hw = blockIdx.x*256 + tid;
    float xv[CC];
    const float* xp = x + ((size_t)b*CC*NA + nn)*HW + hw;
    #pragma unroll
    for (int c = 0; c < CC; c++) xv[c] = xp[(size_t)c*NA*HW];
    float* op = g_sqT + ((size_t)b*DN + nn)*HW + hw;
    for (int dd = 0; dd < CC; dd++) {
        float acc = 0.f;
        #pragma unroll
        for (int c = 0; c < CC; c++) acc += Ws[dd*CC + c] * xv[c];
        op[(size_t)dd*NA*HW] = acc;   // row dd*25+nn
    }
}

// ---------------- spatial KV projection on subsampled xs ----------------
__global__ __launch_bounds__(256) void k_proj_skv(const float* __restrict__ x,
                                                  const float* __restrict__ w) {
    __shared__ float Ws[120*CC];
    int tid = threadIdx.x;
    for (int i = tid; i < 120*CC; i += 256) Ws[i] = w[i];
    __syncthreads();
    int bn = blockIdx.y, b = bn/NA, nn = bn%NA;
    int i2 = blockIdx.x*256 + tid;          // 0..2303
    int h2 = i2/48, w2 = i2%48;
    int src = h2*192 + w2*2;                // (2*h2)*96 + 2*w2
    float xv[CC];
    const float* xp = x + ((size_t)b*CC*NA + nn)*HW + src;
    #pragma unroll
    for (int c = 0; c < CC; c++) xv[c] = xp[(size_t)c*NA*HW];
    float* op = g_skv + ((size_t)b*3000 + nn)*HW2 + i2;
    for (int dd = 0; dd < 120; dd++) {
        float acc = 0.f;
        #pragma unroll
        for (int c = 0; c < CC; c++) acc += Ws[dd*CC + c] * xv[c];
        op[(size_t)dd*NA*HW2] = acc;  // row dd*25+nn (K for dd<60, V for dd>=60)
    }
}

// ---------------- 180-row projection (angular / frequency) ----------------
__global__ __launch_bounds__(256) void k_proj180(const float* __restrict__ x,
                                                 const float* __restrict__ w, int which) {
    __shared__ float Ws[TD*CC];   // 43.2 KB static
    float* outp = which ? g_fqkv : g_aqkv;
    int tid = threadIdx.x;
    for (int i = tid; i < TD*CC; i += 256) Ws[i] = w[i];
    __syncthreads();
    int bn = blockIdx.y, b = bn/NA, nn = bn%NA;
    int hw = blockIdx.x*256 + tid;
    float xv[CC];
    const float* xp = x + ((size_t)b*CC*NA + nn)*HW + hw;
    #pragma unroll
    for (int c = 0; c < CC; c++) xv[c] = xp[(size_t)c*NA*HW];
    float* op = outp + (size_t)b*TD*NHW + (size_t)nn*HW + hw;
    for (int dd = 0; dd < TD; dd++) {
        float acc = 0.f;
        #pragma unroll
        for (int c = 0; c < CC; c++) acc += Ws[dd*CC + c] * xv[c];
        op[(size_t)dd*NHW] = acc;
    }
}

// ---------------- spatial norms ----------------
__global__ __launch_bounds__(256) void k_rq() {
    int b = blockIdx.y;
    int hw = blockIdx.x*256 + threadIdx.x;
    const float* p = g_sqT + (size_t)b*DN*HW + hw;
    float s = 0.f;
    for (int k = 0; k < DN; k++) { float v = p[(size_t)k*HW]; s += v*v; }
    g_rq[b*HW + hw] = 1.f / fmaxf(sqrtf(s), 1e-12f);
}
__global__ __launch_bounds__(256) void k_rk() {
    int b = blockIdx.y;
    int n = blockIdx.x*256 + threadIdx.x;
    const float* p = g_skv + (size_t)b*3000*HW2 + n;
    float s = 0.f;
    for (int k = 0; k < DN; k++) { float v = p[(size_t)k*HW2]; s += v*v; }
    g_rk[b*HW2 + n] = 1.f / fmaxf(sqrtf(s), 1e-12f);
}

// ---------------- GEMM1: S = (Q^T)^T * K, both operands K-major ----------------
// A = g_sqT (K=1500 x M=9216), B = g_skv K-part (K=1500 x N=2304)
__global__ __launch_bounds__(256) void k_gemm1() {
    __shared__ float As[8][128];
    __shared__ float Bs[8][128];
    int b  = blockIdx.z;
    int m0 = blockIdx.y*128;
    int n0 = blockIdx.x*128;
    const float* A  = g_sqT + (size_t)b*DN*HW;
    const float* Bp = g_skv + (size_t)b*3000*HW2;
    int tid = threadIdx.x;
    int la_k = tid >> 5, la_m = (tid & 31)*4;
    int ty = tid >> 4, tx = tid & 15;
    float acc[8][8] = {};
    for (int kt = 0; kt < 1504; kt += 8) {
        int k = kt + la_k;
        float4 av = make_float4(0.f,0.f,0.f,0.f);
        float4 bv = make_float4(0.f,0.f,0.f,0.f);
        if (k < DN) {
            av = *(const float4*)(A  + (size_t)k*HW  + m0 + la_m);
            bv = *(const float4*)(Bp + (size_t)k*HW2 + n0 + la_m);
        }
        __syncthreads();
        *(float4*)&As[la_k][la_m] = av;
        *(float4*)&Bs[la_k][la_m] = bv;
        __syncthreads();
        #pragma unroll
        for (int kk = 0; kk < 8; kk++) {
            float a[8], bb[8];
            *(float4*)(a)    = *(const float4*)(&As[kk][ty*8]);
            *(float4*)(a+4)  = *(const float4*)(&As[kk][ty*8+4]);
            *(float4*)(bb)   = *(const float4*)(&Bs[kk][tx*8]);
            *(float4*)(bb+4) = *(const float4*)(&Bs[kk][tx*8+4]);
            #pragma unroll
            for (int i = 0; i < 8; i++)
                #pragma unroll
                for (int j = 0; j < 8; j++) acc[i][j] += a[i]*bb[j];
        }
    }
    float rkv[8];
    #pragma unroll
    for (int j = 0; j < 8; j++) rkv[j] = g_rk[b*HW2 + n0 + tx*8 + j];
    float* C = g_S + (size_t)b*HW*HW2;
    #pragma unroll
    for (int i = 0; i < 8; i++) {
        int m = m0 + ty*8 + i;
        float rqv = g_rq[b*HW + m];
        float4 v0, v1;
        v0.x = acc[i][0]*rqv*rkv[0]; v0.y = acc[i][1]*rqv*rkv[1];
        v0.z = acc[i][2]*rqv*rkv[2]; v0.w = acc[i][3]*rqv*rkv[3];
        v1.x = acc[i][4]*rqv*rkv[4]; v1.y = acc[i][5]*rqv*rkv[5];
        v1.z = acc[i][6]*rqv*rkv[6]; v1.w = acc[i][7]*rqv*rkv[7];
        *(float4*)(C + (size_t)m*HW2 + n0 + tx*8)     = v0;
        *(float4*)(C + (size_t)m*HW2 + n0 + tx*8 + 4) = v1;
    }
}

// ---------------- row softmax on S (rows of length 2304) ----------------
__global__ __launch_bounds__(256) void k_softmax() {
    __shared__ float row[HW2];
    __shared__ float red[256];
    int b = blockIdx.y, m = blockIdx.x;
    float* p = g_S + ((size_t)b*HW + m)*HW2;
    int tid = threadIdx.x;
    float mx = -1e30f;
    for (int i = tid; i < HW2; i += 256) { float v = p[i]; row[i] = v; mx = fmaxf(mx, v); }
    red[tid] = mx; __syncthreads();
    for (int s = 128; s > 0; s >>= 1) { if (tid < s) red[tid] = fmaxf(red[tid], red[tid+s]); __syncthreads(); }
    mx = red[0]; __syncthreads();
    float sm = 0.f;
    for (int i = tid; i < HW2; i += 256) { float e = __expf(row[i] - mx); row[i] = e; sm += e; }
    red[tid] = sm; __syncthreads();
    for (int s = 128; s > 0; s >>= 1) { if (tid < s) red[tid] += red[tid+s]; __syncthreads(); }
    float inv = 1.f / red[0];
    for (int i = tid; i < HW2; i += 256) p[i] = row[i]*inv;
}

// ---------------- GEMM2: cat[0:1500] = V @ P^T, both operands K-contiguous ----------------
// A = V = g_skv rows 1500..2999 (M=1500 x K=2304), B = P = g_S (N=9216 x K=2304)
__global__ __launch_bounds__(256) void k_gemm2() {
    __shared__ float As[8][132];
    __shared__ float Bs[8][132];
    int b  = blockIdx.z;
    int m0 = blockIdx.y*128;   // 12 tiles, tail at 1500
    int n0 = blockIdx.x*128;   // 72 tiles
    const float* A  = g_skv + (size_t)b*3000*HW2 + (size_t)DN*HW2;
    const float* Bp = g_S   + (size_t)b*HW*HW2;
    int tid = threadIdx.x;
    int lm = tid >> 1, lk = (tid & 1)*4;
    int ty = tid >> 4, tx = tid & 15;
    int gm = m0 + lm;
    bool mok = gm < DN;
    float acc[8][8] = {};
    for (int kt = 0; kt < HW2; kt += 8) {
        float4 av = make_float4(0.f,0.f,0.f,0.f);
        if (mok) av = *(const float4*)(A + (size_t)gm*HW2 + kt + lk);
        float4 bv = *(const float4*)(Bp + (size_t)(n0+lm)*HW2 + kt + lk);
        __syncthreads();
        As[lk+0][lm] = av.x; As[lk+1][lm] = av.y; As[lk+2][lm] = av.z; As[lk+3][lm] = av.w;
        Bs[lk+0][lm] = bv.x; Bs[lk+1][lm] = bv.y; Bs[lk+2][lm] = bv.z; Bs[lk+3][lm] = bv.w;
        __syncthreads();
        #pragma unroll
        for (int kk = 0; kk < 8; kk++) {
            float a[8], bb[8];
            *(float4*)(a)    = *(const float4*)(&As[kk][ty*8]);
            *(float4*)(a+4)  = *(const float4*)(&As[kk][ty*8+4]);
            *(float4*)(bb)   = *(const float4*)(&Bs[kk][tx*8]);
            *(float4*)(bb+4) = *(const float4*)(&Bs[kk][tx*8+4]);
            #pragma unroll
            for (int i = 0; i < 8; i++)
                #pragma unroll
                for (int j = 0; j < 8; j++) acc[i][j] += a[i]*bb[j];
        }
    }
    float* C = g_cat + (size_t)b*4500*HW;
    #pragma unroll
    for (int i = 0; i < 8; i++) {
        int m = m0 + ty*8 + i;
        if (m < DN) {
            float4 v0, v1;
            v0.x = acc[i][0]; v0.y = acc[i][1]; v0.z = acc[i][2]; v0.w = acc[i][3];
            v1.x = acc[i][4]; v1.y = acc[i][5]; v1.z = acc[i][6]; v1.w = acc[i][7];
            *(float4*)(C + (size_t)m*HW + n0 + tx*8)     = v0;
            *(float4*)(C + (size_t)m*HW + n0 + tx*8 + 4) = v1;
        }
    }
}

// ---------------- angular norms: per (b,n) over (dd,hw) ----------------
__global__ __launch_bounds__(256) void k_anorm() {
    __shared__ float red[256];
    int b = blockIdx.x/NA, nn = blockIdx.x%NA;
    int tid = threadIdx.x;
    const float* base = g_aqkv + (size_t)b*TD*NHW + (size_t)nn*HW;
    float sq_ = 0.f, sk_ = 0.f;
    for (int dd = 0; dd < CC; dd++) {
        const float* pq = base + (size_t)dd*NHW;
        const float* pk = base + (size_t)(dd+60)*NHW;
        for (int i = tid; i < HW; i += 256) { float v = pq[i]; sq_ += v*v; v = pk[i]; sk_ += v*v; }
    }
    red[tid] = sq_; __syncthreads();
    for (int s = 128; s > 0; s >>= 1) { if (tid < s) red[tid] += red[tid+s]; __syncthreads(); }
    if (tid == 0) g_aqn[b*NA+nn] = 1.f / fmaxf(sqrtf(red[0]), 1e-12f);
    __syncthreads();
    red[tid] = sk_; __syncthreads();
    for (int s = 128; s > 0; s >>= 1) { if (tid < s) red[tid] += red[tid+s]; __syncthreads(); }
    if (tid == 0) g_akn[b*NA+nn] = 1.f / fmaxf(sqrtf(red[0]), 1e-12f);
}

// ---------------- angular Gram: block per (b,dd), 25x25 over hw ----------------
__global__ __launch_bounds__(256) void k_agram() {
    __shared__ float qs[128*NA];   // [i][n], stride 25 -> conflict-free
    __shared__ float ks[128*NA];
    int b = blockIdx.x/CC, dd = blockIdx.x%CC;
    const float* pq = g_aqkv + (size_t)b*TD*NHW + (size_t)dd*NHW;
    const float* pk = pq + (size_t)60*NHW;
    int tid = threadIdx.x;
    float a0 = 0.f, a1 = 0.f, a2 = 0.f;
    int p0 = tid, p1 = tid+256, p2 = tid+512;
    for (int i0 = 0; i0 < HW; i0 += 128) {
        __syncthreads();
        for (int idx = tid; idx < NA*128; idx += 256) {
            int nn = idx >> 7, i = idx & 127;
            qs[i*NA+nn] = pq[(size_t)nn*HW + i0 + i];
            ks[i*NA+nn] = pk[(size_t)nn*HW + i0 + i];
        }
        __syncthreads();
        if (p0 < 625) { int n1 = p0/NA, n2 = p0%NA; float s = 0.f;
            for (int i = 0; i < 128; i++) s += qs[i*NA+n1]*ks[i*NA+n2]; a0 += s; }
        if (p1 < 625) { int n1 = p1/NA, n2 = p1%NA; float s = 0.f;
            for (int i = 0; i < 128; i++) s += qs[i*NA+n1]*ks[i*NA+n2]; a1 += s; }
        if (p2 < 625) { int n1 = p2/NA, n2 = p2%NA; float s = 0.f;
            for (int i = 0; i < 128; i++) s += qs[i*NA+n1]*ks[i*NA+n2]; a2 += s; }
    }
    if (p0 < 625) atomicAdd(&g_Ga[b*625 + p0], a0);
    if (p1 < 625) atomicAdd(&g_Ga[b*625 + p1], a1);
    if (p2 < 625) atomicAdd(&g_Ga[b*625 + p2], a2);
}

// ---------------- angular softmax (warp per row) ----------------
__global__ void k_asoft() {
    int b = blockIdx.x/NA, n1 = blockIdx.x%NA;
    int lane = threadIdx.x;
    float g = 0.f, v = -1e30f;
    if (lane < NA) { g = g_Ga[(b*NA+n1)*NA + lane] * g_aqn[b*NA+n1] * g_akn[b*NA+lane]; v = g; }
    for (int s = 16; s > 0; s >>= 1) v = fmaxf(v, __shfl_xor_sync(0xffffffffu, v, s));
    float e = (lane < NA) ? __expf(g - v) : 0.f;
    float sm = e;
    for (int s = 16; s > 0; s >>= 1) sm += __shfl_xor_sync(0xffffffffu, sm, s);
    if (lane < NA) g_Aatt[(b*NA+n1)*NA + lane] = e/sm;
}

// ---------------- angular apply: cat[60..119] ----------------
__global__ __launch_bounds__(256) void k_aapply() {
    __shared__ float att[NA*NA];   // transposed: att[n2*25+n1]
    int tid = threadIdx.x;
    int b = blockIdx.z, dd = blockIdx.y;
    for (int i = tid; i < NA*NA; i += 256) {
        int n2 = i/NA, n1 = i%NA;
        att[i] = g_Aatt[b*625 + n1*NA + n2];
    }
    __syncthreads();
    int hw = blockIdx.x*256 + tid;
    const float* v = g_aqkv + (size_t)b*TD*NHW + (size_t)(120+dd)*NHW + hw;
    float acc[NA] = {};
    for (int n2 = 0; n2 < NA; n2++) {
        float vv = v[(size_t)n2*HW];
        #pragma unroll
        for (int n1 = 0; n1 < NA; n1++) acc[n1] += att[n2*NA+n1]*vv;
    }
    float* o = g_cat + (size_t)b*4500*HW + (size_t)(60+dd)*NHW + hw;
    #pragma unroll
    for (int n1 = 0; n1 < NA; n1++) o[(size_t)n1*HW] = acc[n1];
}

// ---------------- frequency norms: per (b,dd), contiguous nhw ----------------
__global__ __launch_bounds__(256) void k_fnorm() {
    __shared__ float red[256];
    int b = blockIdx.x/CC, dd = blockIdx.x%CC;
    int tid = threadIdx.x;
    const float* pq = g_fqkv + (size_t)b*TD*NHW + (size_t)dd*NHW;
    const float* pk = pq + (size_t)60*NHW;
    float sq_ = 0.f, sk_ = 0.f;
    for (int i = tid; i < NHW; i += 256) { float v = pq[i]; sq_ += v*v; v = pk[i]; sk_ += v*v; }
    red[tid] = sq_; __syncthreads();
    for (int s = 128; s > 0; s >>= 1) { if (tid < s) red[tid] += red[tid+s]; __syncthreads(); }
    if (tid == 0) g_fqn[b*CC+dd] = 1.f / fmaxf(sqrtf(red[0]), 1e-12f);
    __syncthreads();
    red[tid] = sk_; __syncthreads();
    for (int s = 128; s > 0; s >>= 1) { if (tid < s) red[tid] += red[tid+s]; __syncthreads(); }
    if (tid == 0) g_fkn[b*CC+dd] = 1.f / fmaxf(sqrtf(red[0]), 1e-12f);
}

// ---------------- frequency Gram: 60x60 over nhw, tiled mini-GEMM ----------------
__global__ __launch_bounds__(256) void k_fgram() {
    __shared__ float qs[64*65];  // [i][d] padded
    __shared__ float ks[64*65];
    int b = blockIdx.y;
    int i0 = blockIdx.x*2304;    // 100 chunks
    const float* base = g_fqkv + (size_t)b*TD*NHW;
    int tid = threadIdx.x, ty = tid >> 4, tx = tid & 15;
    float acc[4][4] = {};
    for (int it = 0; it < 2304; it += 64) {
        __syncthreads();
        for (int idx = tid; idx < 64*CC; idx += 256) {
            int d = idx >> 6, i = idx & 63;
            qs[i*65+d] = base[(size_t)d*NHW + i0 + it + i];
            ks[i*65+d] = base[(size_t)(60+d)*NHW + i0 + it + i];
        }
        __syncthreads();
        for (int i = 0; i < 64; i++) {
            float a[4], bb[4];
            #pragma unroll
            for (int r = 0; r < 4; r++) { a[r] = qs[i*65 + ty*4 + r]; bb[r] = ks[i*65 + tx*4 + r]; }
            #pragma unroll
            for (int r = 0; r < 4; r++)
                #pragma unroll
                for (int c = 0; c < 4; c++) acc[r][c] += a[r]*bb[c];
        }
    }
    #pragma unroll
    for (int r = 0; r < 4; r++) {
        int d1 = ty*4 + r; if (d1 >= CC) continue;
        #pragma unroll
        for (int c = 0; c < 4; c++) {
            int d2 = tx*4 + c; if (d2 >= CC) continue;
            atomicAdd(&g_Gf[(b*CC + d1)*CC + d2], acc[r][c]);
        }
    }
}

// ---------------- frequency softmax ----------------
__global__ void k_fsoft() {
    __shared__ float red[64];
    int b = blockIdx.x/CC, d1 = blockIdx.x%CC;
    int t = threadIdx.x;
    float g = 0.f, v = -1e30f;
    if (t < CC) { g = g_Gf[(b*CC+d1)*CC + t] * g_fqn[b*CC+d1] * g_fkn[b*CC+t]; v = g; }
    red[t] = v; __syncthreads();
    for (int s = 32; s > 0; s >>= 1) { if (t < s) red[t] = fmaxf(red[t], red[t+s]); __syncthreads(); }
    float mx = red[0]; __syncthreads();
    float e = (t < CC) ? __expf(g - mx) : 0.f;
    red[t] = e; __syncthreads();
    for (int s = 32; s > 0; s >>= 1) { if (t < s) red[t] += red[t+s]; __syncthreads(); }
    if (t < CC) g_Fatt[(b*CC+d1)*CC + t] = e/red[0];
}

// ---------------- frequency apply: cat[120..179] ----------------
__global__ __launch_bounds__(256) void k_fapply() {
    __shared__ float att[CC*CC];   // transposed: att[d2*60+d1]
    int tid = threadIdx.x;
    int b = blockIdx.y;
    for (int i = tid; i < CC*CC; i += 256) {
        int d2 = i/CC, d1 = i%CC;
        att[i] = g_Fatt[b*CC*CC + d1*CC + d2];
    }
    __syncthreads();
    size_t i = (size_t)blockIdx.x*256 + tid;   // over NHW
    const float* v = g_fqkv + (size_t)b*TD*NHW + (size_t)120*NHW + i;
    float acc[CC] = {};
    for (int d2 = 0; d2 < CC; d2++) {
        float vv = v[(size_t)d2*NHW];
        #pragma unroll
        for (int d1 = 0; d1 < CC; d1++) acc[d1] += att[d2*CC+d1]*vv;
    }
    float* o = g_cat + (size_t)b*4500*HW + (size_t)120*NHW + i;
    #pragma unroll
    for (int d1 = 0; d1 < CC; d1++) o[(size_t)d1*NHW] = acc[d1];
}

// ---------------- fused LayerNorm + MLP + residual ----------------
__global__ __launch_bounds__(256) void k_lnmlp(const float* __restrict__ x,
                                               const float* __restrict__ gamma,
                                               const float* __restrict__ beta,
                                               const float* __restrict__ w1,
                                               const float* __restrict__ w2,
                                               float* __restrict__ out) {
    extern __shared__ float dynsm[];
    float* W1s = dynsm;              // [ch*60+dd] = w1[dd*180+ch]  (10800)
    float* W2s = W1s + TD*CC;        // direct copy of w2 (3600): [c*60+h]
    float* gs  = W2s + CC*CC;        // 180
    float* bs  = gs + TD;            // 180
    int tid = threadIdx.x;
    for (int idx = tid; idx < TD*CC; idx += 256) {
        int dd = idx % CC, ch = idx / CC;
        W1s[idx] = w1[dd*TD + ch];
    }
    for (int idx = tid; idx < CC*CC; idx += 256) W2s[idx] = w2[idx];
    for (int idx = tid; idx < TD; idx += 256) { gs[idx] = gamma[idx]; bs[idx] = beta[idx]; }
    __syncthreads();
    int b = blockIdx.y;
    size_t i = (size_t)blockIdx.x*256 + tid;     // over NHW
    const float* cp = g_cat + (size_t)b*4500*HW + i;
    float s = 0.f, ss = 0.f;
    for (int ch = 0; ch < TD; ch++) { float v = cp[(size_t)ch*NHW]; s += v; ss += v*v; }
    float mu = s * (1.f/TD);
    float var = ss * (1.f/TD) - mu*mu;
    float inv = rsqrtf(var + 1e-5f);
    float hv[CC] = {};
    for (int ch = 0; ch < TD; ch++) {
        float v = (cp[(size_t)ch*NHW] - mu)*inv*gs[ch] + bs[ch];
        #pragma unroll
        for (int dd = 0; dd < CC; dd++) hv[dd] += W1s[ch*CC + dd]*v;
    }
    #pragma unroll
    for (int dd = 0; dd < CC; dd++) hv[dd] = fmaxf(hv[dd], 0.f);
    const float* xb = x + (size_t)b*CC*NHW;
    float* ob = out + (size_t)b*CC*NHW;
    for (int c = 0; c < CC; c++) {
        float acc = 0.f;
        #pragma unroll
        for (int h = 0; h < CC; h++) acc += W2s[c*CC + h]*hv[h];
        ob[(size_t)c*NHW + i] = acc + xb[(size_t)c*NHW + i];
    }
}

// ---------------- launch ----------------
extern "C" void kernel_launch(void* const* d_in, const int* in_sizes, int n_in,
                              void* d_out, int out_size) {
    const float* x    = (const float*)d_in[0];
    const float* wsq  = (const float*)d_in[1];
    const float* wskv = (const float*)d_in[2];
    const float* waq  = (const float*)d_in[3];
    const float* wfq  = (const float*)d_in[4];
    const float* gam  = (const float*)d_in[5];
    const float* bet  = (const float*)d_in[6];
    const float* w1   = (const float*)d_in[7];
    const float* w2   = (const float*)d_in[8];
    float* out = (float*)d_out;

    cudaFuncSetAttribute(k_lnmlp, cudaFuncAttributeMaxDynamicSharedMemorySize, 59040);

    k_zero    <<<57, 256>>>();
    k_proj_sq <<<dim3(36,100), 256>>>(x, wsq);
    k_proj_skv<<<dim3(9,100),  256>>>(x, wskv);
    k_proj180 <<<dim3(36,100), 256>>>(x, waq, 0);
    k_proj180 <<<dim3(36,100), 256>>>(x, wfq, 1);
    k_rq      <<<dim3(36,BN),  256>>>();
    k_rk      <<<dim3(9,BN),   256>>>();
    k_gemm1   <<<dim3(18,72,BN), 256>>>();
    k_softmax <<<dim3(HW,BN),  256>>>();
    k_gemm2   <<<dim3(72,12,BN), 256>>>();
    k_anorm   <<<BN*NA, 256>>>();
    k_agram   <<<BN*CC, 256>>>();
    k_asoft   <<<BN*NA, 32>>>();
    k_aapply  <<<dim3(36,CC,BN), 256>>>();
    k_fnorm   <<<BN*CC, 256>>>();
    k_fgram   <<<dim3(100,BN), 256>>>();
    k_fsoft   <<<BN*CC, 64>>>();
    k_fapply  <<<dim3(900,BN), 256>>>();
    k_lnmlp   <<<dim3(900,BN), 256, 59040>>>(x, gam, bet, w1, w2, out);
}

// round 13
// speedup vs baseline: 1.8999x; 1.8999x over previous
#include <cuda_runtime.h>
#include <cuda_bf16.h>
#include <math.h>

#define BN 4
#define CC 60
#define NA 25
#define HW 9216
#define HW2 2304
#define DN 1500
#define NHW 230400   // NA*HW
#define TD 180

typedef __nv_bfloat16 bf16;
typedef unsigned int uint;

// ---------------- scratch: __device__ globals (allocation-free) ----------------
static __device__ __align__(16) bf16  g_Qb  [(size_t)BN*DN*HW];    // (b, dn, hw)  K-major Q for GEMM1
static __device__ __align__(16) bf16  g_Kb  [(size_t)BN*DN*HW2];   // (b, dn, hw2) K-major K for GEMM1
static __device__ __align__(16) bf16  g_Vb  [(size_t)BN*DN*HW2];   // (b, dn, hw2) row-major V for GEMM2
static __device__ __align__(16) bf16  g_S   [(size_t)BN*HW*HW2];   // scores -> probs (bf16, in place)
static __device__ __align__(16) float g_aqkv[(size_t)BN*TD*NHW];   // (b, 180, n, hw)
static __device__ __align__(16) float g_fqkv[(size_t)BN*TD*NHW];   // (b, 180, n*hw)
static __device__ __align__(16) float g_cat [(size_t)BN*4500*HW];  // (b, 180*25, hw)
static __device__ float g_rq[BN*HW];
static __device__ float g_rk[BN*HW2];
static __device__ float g_aqn[BN*NA], g_akn[BN*NA];
static __device__ float g_fqn[BN*CC], g_fkn[BN*CC];
static __device__ float g_Ga[BN*NA*NA], g_Aatt[BN*NA*NA];
static __device__ float g_Gf[BN*CC*CC], g_Fatt[BN*CC*CC];

// ---------------- zero Gram accumulators ----------------
__global__ void k_zero() {
    int i = blockIdx.x*256 + threadIdx.x;
    if (i < BN*NA*NA) g_Ga[i] = 0.f;
    if (i < BN*CC*CC) g_Gf[i] = 0.f;
}

// ---------------- spatial Q projection -> bf16, row dd*25+nn ----------------
__global__ __launch_bounds__(256) void k_proj_sq(const float* __restrict__ x,
                                                 const float* __restrict__ w) {
    __shared__ float Ws[CC*CC];
    int tid = threadIdx.x;
    for (int i = tid; i < CC*CC; i += 256) Ws[i] = w[i];
    __syncthreads();
    int bn = blockIdx.y, b = bn/NA, nn = bn%NA;
    int hw = blockIdx.x*256 + tid;
    float xv[CC];
    const float* xp = x + ((size_t)b*CC*NA + nn)*HW + hw;
    #pragma unroll
    for (int c = 0; c < CC; c++) xv[c] = xp[(size_t)c*NA*HW];
    bf16* op = g_Qb + ((size_t)b*DN + nn)*HW + hw;
    for (int dd = 0; dd < CC; dd++) {
        float acc = 0.f;
        #pragma unroll
        for (int c = 0; c < CC; c++) acc += Ws[dd*CC + c] * xv[c];
        op[(size_t)dd*NA*HW] = __float2bfloat16_rn(acc);
    }
}

// ---------------- spatial KV projection on subsampled xs -> bf16 K and V ----------------
__global__ __launch_bounds__(256) void k_proj_skv(const float* __restrict__ x,
                                                  const float* __restrict__ w) {
    __shared__ float Ws[120*CC];
    int tid = threadIdx.x;
    for (int i = tid; i < 120*CC; i += 256) Ws[i] = w[i];
    __syncthreads();
    int bn = blockIdx.y, b = bn/NA, nn = bn%NA;
    int i2 = blockIdx.x*256 + tid;          // 0..2303
    int h2 = i2/48, w2 = i2%48;
    int src = h2*192 + w2*2;
    float xv[CC];
    const float* xp = x + ((size_t)b*CC*NA + nn)*HW + src;
    #pragma unroll
    for (int c = 0; c < CC; c++) xv[c] = xp[(size_t)c*NA*HW];
    bf16* opk = g_Kb + ((size_t)b*DN + nn)*HW2 + i2;
    bf16* opv = g_Vb + ((size_t)b*DN + nn)*HW2 + i2;
    for (int dd = 0; dd < 60; dd++) {
        float acc = 0.f;
        #pragma unroll
        for (int c = 0; c < CC; c++) acc += Ws[dd*CC + c] * xv[c];
        opk[(size_t)dd*NA*HW2] = __float2bfloat16_rn(acc);
    }
    for (int dd = 60; dd < 120; dd++) {
        float acc = 0.f;
        #pragma unroll
        for (int c = 0; c < CC; c++) acc += Ws[dd*CC + c] * xv[c];
        opv[(size_t)(dd-60)*NA*HW2] = __float2bfloat16_rn(acc);
    }
}

// ---------------- 180-row projection (angular / frequency), fp32 ----------------
__global__ __launch_bounds__(256) void k_proj180(const float* __restrict__ x,
                                                 const float* __restrict__ w, int which) {
    __shared__ float Ws[TD*CC];
    float* outp = which ? g_fqkv : g_aqkv;
    int tid = threadIdx.x;
    for (int i = tid; i < TD*CC; i += 256) Ws[i] = w[i];
    __syncthreads();
    int bn = blockIdx.y, b = bn/NA, nn = bn%NA;
    int hw = blockIdx.x*256 + tid;
    float xv[CC];
    const float* xp = x + ((size_t)b*CC*NA + nn)*HW + hw;
    #pragma unroll
    for (int c = 0; c < CC; c++) xv[c] = xp[(size_t)c*NA*HW];
    float* op = outp + (size_t)b*TD*NHW + (size_t)nn*HW + hw;
    for (int dd = 0; dd < TD; dd++) {
        float acc = 0.f;
        #pragma unroll
        for (int c = 0; c < CC; c++) acc += Ws[dd*CC + c] * xv[c];
        op[(size_t)dd*NHW] = acc;
    }
}

// ---------------- spatial norms (from the bf16 operands) ----------------
__global__ __launch_bounds__(256) void k_rq() {
    int b = blockIdx.y;
    int hw = blockIdx.x*256 + threadIdx.x;
    const bf16* p = g_Qb + (size_t)b*DN*HW + hw;
    float s = 0.f;
    for (int k = 0; k < DN; k++) { float v = __bfloat162float(p[(size_t)k*HW]); s += v*v; }
    g_rq[b*HW + hw] = 1.f / fmaxf(sqrtf(s), 1e-12f);
}
__global__ __launch_bounds__(256) void k_rk() {
    int b = blockIdx.y;
    int n = blockIdx.x*256 + threadIdx.x;
    const bf16* p = g_Kb + (size_t)b*DN*HW2 + n;
    float s = 0.f;
    for (int k = 0; k < DN; k++) { float v = __bfloat162float(p[(size_t)k*HW2]); s += v*v; }
    g_rk[b*HW2 + n] = 1.f / fmaxf(sqrtf(s), 1e-12f);
}

// ---------------- mma helper ----------------
__device__ __forceinline__ void mma16816(float* c, const uint* a, const uint* b) {
    asm volatile("mma.sync.aligned.m16n8k16.row.col.f32.bf16.bf16.f32 "
        "{%0,%1,%2,%3}, {%4,%5,%6,%7}, {%8,%9}, {%0,%1,%2,%3};\n"
        : "+f"(c[0]), "+f"(c[1]), "+f"(c[2]), "+f"(c[3])
        : "r"(a[0]), "r"(a[1]), "r"(a[2]), "r"(a[3]), "r"(b[0]), "r"(b[1]));
}

#define PADK 40   // smem k-stride (bf16): 80B = 5*16B aligned, conflict-free fragments

// ---------------- GEMM1 (bf16 mma): S[m=hw][n=hw2] = sum_dn Q[dn][m] K[dn][n] ----------------
// A,B global K-major -> transpose into smem [m][k]/[n][k]. Epilogue: *rq[m]*rk[n], write bf16.
__global__ __launch_bounds__(256) void k_gemm1() {
    __shared__ bf16 As[128][PADK];
    __shared__ bf16 Bs[128][PADK];
    int b  = blockIdx.z;
    int m0 = blockIdx.y*128;
    int n0 = blockIdx.x*128;
    const bf16* A  = g_Qb + (size_t)b*DN*HW;
    const bf16* Bp = g_Kb + (size_t)b*DN*HW2;
    int tid = threadIdx.x;
    int wid = tid >> 5, lane = tid & 31;
    int wm = wid & 3, wn = wid >> 2;          // warps 4(M) x 2(N); warp tile 32x64
    int g = lane >> 2, tig = lane & 3;
    int kr = tid >> 3;                        // load: 32 k-rows
    int c0l = (tid & 7)*16;                   // 8 threads x 16 elems cover 128
    float acc[2][8][4] = {};
    for (int kt = 0; kt < 1504; kt += 32) {
        int kg = kt + kr;
        uint4 av0 = {0,0,0,0}, av1 = {0,0,0,0}, bv0 = {0,0,0,0}, bv1 = {0,0,0,0};
        if (kg < DN) {
            const uint4* ap = (const uint4*)(A  + (size_t)kg*HW  + m0 + c0l);
            av0 = ap[0]; av1 = ap[1];
            const uint4* bp = (const uint4*)(Bp + (size_t)kg*HW2 + n0 + c0l);
            bv0 = bp[0]; bv1 = bp[1];
        }
        __syncthreads();
        {
            const bf16* a16 = (const bf16*)&av0;
            const bf16* b16 = (const bf16*)&bv0;
            #pragma unroll
            for (int i = 0; i < 8; i++) { As[c0l+i][kr] = a16[i]; Bs[c0l+i][kr] = b16[i]; }
            a16 = (const bf16*)&av1; b16 = (const bf16*)&bv1;
            #pragma unroll
            for (int i = 0; i < 8; i++) { As[c0l+8+i][kr] = a16[i]; Bs[c0l+8+i][kr] = b16[i]; }
        }
        __syncthreads();
        #pragma unroll
        for (int kk = 0; kk < 32; kk += 16) {
            uint af[2][4], bfr[8][2];
            #pragma unroll
            for (int mt = 0; mt < 2; mt++) {
                int mm = wm*32 + mt*16 + g;
                af[mt][0] = *(const uint*)&As[mm  ][kk + tig*2];
                af[mt][1] = *(const uint*)&As[mm+8][kk + tig*2];
                af[mt][2] = *(const uint*)&As[mm  ][kk + tig*2 + 8];
                af[mt][3] = *(const uint*)&As[mm+8][kk + tig*2 + 8];
            }
            #pragma unroll
            for (int nt = 0; nt < 8; nt++) {
                int nn = wn*64 + nt*8 + g;
                bfr[nt][0] = *(const uint*)&Bs[nn][kk + tig*2];
                bfr[nt][1] = *(const uint*)&Bs[nn][kk + tig*2 + 8];
            }
            #pragma unroll
            for (int mt = 0; mt < 2; mt++)
                #pragma unroll
                for (int nt = 0; nt < 8; nt++) mma16816(acc[mt][nt], af[mt], bfr[nt]);
        }
    }
    bf16* S = g_S + (size_t)b*HW*HW2;
    #pragma unroll
    for (int mt = 0; mt < 2; mt++) {
        int m = m0 + wm*32 + mt*16 + g;
        float rq0 = g_rq[b*HW + m], rq1 = g_rq[b*HW + m + 8];
        #pragma unroll
        for (int nt = 0; nt < 8; nt++) {
            int n = n0 + wn*64 + nt*8 + tig*2;
            float rk0 = g_rk[b*HW2 + n], rk1 = g_rk[b*HW2 + n + 1];
            float* c = acc[mt][nt];
            *(__nv_bfloat162*)&S[(size_t)m*HW2 + n] =
                __floats2bfloat162_rn(c[0]*rq0*rk0, c[1]*rq0*rk1);
            *(__nv_bfloat162*)&S[(size_t)(m+8)*HW2 + n] =
                __floats2bfloat162_rn(c[2]*rq1*rk0, c[3]*rq1*rk1);
        }
    }
}

// ---------------- row softmax on S (bf16 in, bf16 out, fp32 internal) ----------------
__global__ __launch_bounds__(256) void k_softmax() {
    __shared__ float row[HW2];
    __shared__ float red[256];
    int b = blockIdx.y, m = blockIdx.x;
    bf16* p = g_S + ((size_t)b*HW + m)*HW2;
    int tid = threadIdx.x;
    float mx = -1e30f;
    for (int i = tid; i < HW2; i += 256) {
        float v = __bfloat162float(p[i]); row[i] = v; mx = fmaxf(mx, v);
    }
    red[tid] = mx; __syncthreads();
    for (int s = 128; s > 0; s >>= 1) { if (tid < s) red[tid] = fmaxf(red[tid], red[tid+s]); __syncthreads(); }
    mx = red[0]; __syncthreads();
    float sm = 0.f;
    for (int i = tid; i < HW2; i += 256) { float e = __expf(row[i] - mx); row[i] = e; sm += e; }
    red[tid] = sm; __syncthreads();
    for (int s = 128; s > 0; s >>= 1) { if (tid < s) red[tid] += red[tid+s]; __syncthreads(); }
    float inv = 1.f / red[0];
    for (int i = tid; i < HW2; i += 256) p[i] = __float2bfloat16_rn(row[i]*inv);
}

// ---------------- GEMM2 (bf16 mma): cat[m=dn][n=hw] = sum_hw2 V[m][k] P[n][k] ----------------
// Both operands row-major with k contiguous -> direct smem copy.
__global__ __launch_bounds__(256) void k_gemm2() {
    __shared__ bf16 As[128][PADK];
    __shared__ bf16 Bs[128][PADK];
    int b  = blockIdx.z;
    int m0 = blockIdx.y*128;   // 12 tiles (tail at 1500)
    int n0 = blockIdx.x*128;   // 72 tiles
    const bf16* A  = g_Vb + (size_t)b*DN*HW2;
    const bf16* Bp = g_S  + (size_t)b*HW*HW2;
    int tid = threadIdx.x;
    int wid = tid >> 5, lane = tid & 31;
    int wm = wid & 3, wn = wid >> 2;
    int g = lane >> 2, tig = lane & 3;
    int lrow = tid >> 1;                 // 128 rows, 2 threads per row
    int k0l = (tid & 1)*16;
    bool mok = (m0 + lrow) < DN;
    float acc[2][8][4] = {};
    for (int kt = 0; kt < HW2; kt += 32) {
        uint4 av0 = {0,0,0,0}, av1 = {0,0,0,0};
        if (mok) {
            const uint4* ap = (const uint4*)(A + (size_t)(m0+lrow)*HW2 + kt + k0l);
            av0 = ap[0]; av1 = ap[1];
        }
        const uint4* bp = (const uint4*)(Bp + (size_t)(n0+lrow)*HW2 + kt + k0l);
        uint4 bv0 = bp[0], bv1 = bp[1];
        __syncthreads();
        *(uint4*)&As[lrow][k0l]   = av0;
        *(uint4*)&As[lrow][k0l+8] = av1;
        *(uint4*)&Bs[lrow][k0l]   = bv0;
        *(uint4*)&Bs[lrow][k0l+8] = bv1;
        __syncthreads();
        #pragma unroll
        for (int kk = 0; kk < 32; kk += 16) {
            uint af[2][4], bfr[8][2];
            #pragma unroll
            for (int mt = 0; mt < 2; mt++) {
                int mm = wm*32 + mt*16 + g;
                af[mt][0] = *(const uint*)&As[mm  ][kk + tig*2];
                af[mt][1] = *(const uint*)&As[mm+8][kk + tig*2];
                af[mt][2] = *(const uint*)&As[mm  ][kk + tig*2 + 8];
                af[mt][3] = *(const uint*)&As[mm+8][kk + tig*2 + 8];
            }
            #pragma unroll
            for (int nt = 0; nt < 8; nt++) {
                int nn = wn*64 + nt*8 + g;
                bfr[nt][0] = *(const uint*)&Bs[nn][kk + tig*2];
                bfr[nt][1] = *(const uint*)&Bs[nn][kk + tig*2 + 8];
            }
            #pragma unroll
            for (int mt = 0; mt < 2; mt++)
                #pragma unroll
                for (int nt = 0; nt < 8; nt++) mma16816(acc[mt][nt], af[mt], bfr[nt]);
        }
    }
    float* C = g_cat + (size_t)b*4500*HW;
    #pragma unroll
    for (int mt = 0; mt < 2; mt++) {
        int m = m0 + wm*32 + mt*16 + g;
        #pragma unroll
        for (int nt = 0; nt < 8; nt++) {
            int n = n0 + wn*64 + nt*8 + tig*2;
            float* c = acc[mt][nt];
            if (m < DN)     { float2 v = {c[0], c[1]}; *(float2*)&C[(size_t)m*HW + n] = v; }
            if (m + 8 < DN) { float2 v = {c[2], c[3]}; *(float2*)&C[(size_t)(m+8)*HW + n] = v; }
        }
    }
}

// ---------------- angular norms ----------------
__global__ __launch_bounds__(256) void k_anorm() {
    __shared__ float red[256];
    int b = blockIdx.x/NA, nn = blockIdx.x%NA;
    int tid = threadIdx.x;
    const float* base = g_aqkv + (size_t)b*TD*NHW + (size_t)nn*HW;
    float sq_ = 0.f, sk_ = 0.f;
    for (int dd = 0; dd < CC; dd++) {
        const float* pq = base + (size_t)dd*NHW;
        const float* pk = base + (size_t)(dd+60)*NHW;
        for (int i = tid; i < HW; i += 256) { float v = pq[i]; sq_ += v*v; v = pk[i]; sk_ += v*v; }
    }
    red[tid] = sq_; __syncthreads();
    for (int s = 128; s > 0; s >>= 1) { if (tid < s) red[tid] += red[tid+s]; __syncthreads(); }
    if (tid == 0) g_aqn[b*NA+nn] = 1.f / fmaxf(sqrtf(red[0]), 1e-12f);
    __syncthreads();
    red[tid] = sk_; __syncthreads();
    for (int s = 128; s > 0; s >>= 1) { if (tid < s) red[tid] += red[tid+s]; __syncthreads(); }
    if (tid == 0) g_akn[b*NA+nn] = 1.f / fmaxf(sqrtf(red[0]), 1e-12f);
}

// ---------------- angular Gram ----------------
__global__ __launch_bounds__(256) void k_agram() {
    __shared__ float qs[128*NA];
    __shared__ float ks[128*NA];
    int b = blockIdx.x/CC, dd = blockIdx.x%CC;
    const float* pq = g_aqkv + (size_t)b*TD*NHW + (size_t)dd*NHW;
    const float* pk = pq + (size_t)60*NHW;
    int tid = threadIdx.x;
    float a0 = 0.f, a1 = 0.f, a2 = 0.f;
    int p0 = tid, p1 = tid+256, p2 = tid+512;
    for (int i0 = 0; i0 < HW; i0 += 128) {
        __syncthreads();
        for (int idx = tid; idx < NA*128; idx += 256) {
            int nn = idx >> 7, i = idx & 127;
            qs[i*NA+nn] = pq[(size_t)nn*HW + i0 + i];
            ks[i*NA+nn] = pk[(size_t)nn*HW + i0 + i];
        }
        __syncthreads();
        if (p0 < 625) { int n1 = p0/NA, n2 = p0%NA; float s = 0.f;
            for (int i = 0; i < 128; i++) s += qs[i*NA+n1]*ks[i*NA+n2]; a0 += s; }
        if (p1 < 625) { int n1 = p1/NA, n2 = p1%NA; float s = 0.f;
            for (int i = 0; i < 128; i++) s += qs[i*NA+n1]*ks[i*NA+n2]; a1 += s; }
        if (p2 < 625) { int n1 = p2/NA, n2 = p2%NA; float s = 0.f;
            for (int i = 0; i < 128; i++) s += qs[i*NA+n1]*ks[i*NA+n2]; a2 += s; }
    }
    if (p0 < 625) atomicAdd(&g_Ga[b*625 + p0], a0);
    if (p1 < 625) atomicAdd(&g_Ga[b*625 + p1], a1);
    if (p2 < 625) atomicAdd(&g_Ga[b*625 + p2], a2);
}

// ---------------- angular softmax ----------------
__global__ void k_asoft() {
    int b = blockIdx.x/NA, n1 = blockIdx.x%NA;
    int lane = threadIdx.x;
    float g = 0.f, v = -1e30f;
    if (lane < NA) { g = g_Ga[(b*NA+n1)*NA + lane] * g_aqn[b*NA+n1] * g_akn[b*NA+lane]; v = g; }
    for (int s = 16; s > 0; s >>= 1) v = fmaxf(v, __shfl_xor_sync(0xffffffffu, v, s));
    float e = (lane < NA) ? __expf(g - v) : 0.f;
    float sm = e;
    for (int s = 16; s > 0; s >>= 1) sm += __shfl_xor_sync(0xffffffffu, sm, s);
    if (lane < NA) g_Aatt[(b*NA+n1)*NA + lane] = e/sm;
}

// ---------------- angular apply ----------------
__global__ __launch_bounds__(256) void k_aapply() {
    __shared__ float att[NA*NA];
    int tid = threadIdx.x;
    int b = blockIdx.z, dd = blockIdx.y;
    for (int i = tid; i < NA*NA; i += 256) {
        int n2 = i/NA, n1 = i%NA;
        att[i] = g_Aatt[b*625 + n1*NA + n2];
    }
    __syncthreads();
    int hw = blockIdx.x*256 + tid;
    const float* v = g_aqkv + (size_t)b*TD*NHW + (size_t)(120+dd)*NHW + hw;
    float acc[NA] = {};
    for (int n2 = 0; n2 < NA; n2++) {
        float vv = v[(size_t)n2*HW];
        #pragma unroll
        for (int n1 = 0; n1 < NA; n1++) acc[n1] += att[n2*NA+n1]*vv;
    }
    float* o = g_cat + (size_t)b*4500*HW + (size_t)(60+dd)*NHW + hw;
    #pragma unroll
    for (int n1 = 0; n1 < NA; n1++) o[(size_t)n1*HW] = acc[n1];
}

// ---------------- frequency norms ----------------
__global__ __launch_bounds__(256) void k_fnorm() {
    __shared__ float red[256];
    int b = blockIdx.x/CC, dd = blockIdx.x%CC;
    int tid = threadIdx.x;
    const float* pq = g_fqkv + (size_t)b*TD*NHW + (size_t)dd*NHW;
    const float* pk = pq + (size_t)60*NHW;
    float sq_ = 0.f, sk_ = 0.f;
    for (int i = tid; i < NHW; i += 256) { float v = pq[i]; sq_ += v*v; v = pk[i]; sk_ += v*v; }
    red[tid] = sq_; __syncthreads();
    for (int s = 128; s > 0; s >>= 1) { if (tid < s) red[tid] += red[tid+s]; __syncthreads(); }
    if (tid == 0) g_fqn[b*CC+dd] = 1.f / fmaxf(sqrtf(red[0]), 1e-12f);
    __syncthreads();
    red[tid] = sk_; __syncthreads();
    for (int s = 128; s > 0; s >>= 1) { if (tid < s) red[tid] += red[tid+s]; __syncthreads(); }
    if (tid == 0) g_fkn[b*CC+dd] = 1.f / fmaxf(sqrtf(red[0]), 1e-12f);
}

// ---------------- frequency Gram ----------------
__global__ __launch_bounds__(256) void k_fgram() {
    __shared__ float qs[64*65];
    __shared__ float ks[64*65];
    int b = blockIdx.y;
    int i0 = blockIdx.x*2304;
    const float* base = g_fqkv + (size_t)b*TD*NHW;
    int tid = threadIdx.x, ty = tid >> 4, tx = tid & 15;
    float acc[4][4] = {};
    for (int it = 0; it < 2304; it += 64) {
        __syncthreads();
        for (int idx = tid; idx < 64*CC; idx += 256) {
            int d = idx >> 6, i = idx & 63;
            qs[i*65+d] = base[(size_t)d*NHW + i0 + it + i];
            ks[i*65+d] = base[(size_t)(60+d)*NHW + i0 + it + i];
        }
        __syncthreads();
        for (int i = 0; i < 64; i++) {
            float a[4], bb[4];
            #pragma unroll
            for (int r = 0; r < 4; r++) { a[r] = qs[i*65 + ty*4 + r]; bb[r] = ks[i*65 + tx*4 + r]; }
            #pragma unroll
            for (int r = 0; r < 4; r++)
                #pragma unroll
                for (int c = 0; c < 4; c++) acc[r][c] += a[r]*bb[c];
        }
    }
    #pragma unroll
    for (int r = 0; r < 4; r++) {
        int d1 = ty*4 + r; if (d1 >= CC) continue;
        #pragma unroll
        for (int c = 0; c < 4; c++) {
            int d2 = tx*4 + c; if (d2 >= CC) continue;
            atomicAdd(&g_Gf[(b*CC + d1)*CC + d2], acc[r][c]);
        }
    }
}

// ---------------- frequency softmax ----------------
__global__ void k_fsoft() {
    __shared__ float red[64];
    int b = blockIdx.x/CC, d1 = blockIdx.x%CC;
    int t = threadIdx.x;
    float g = 0.f, v = -1e30f;
    if (t < CC) { g = g_Gf[(b*CC+d1)*CC + t] * g_fqn[b*CC+d1] * g_fkn[b*CC+t]; v = g; }
    red[t] = v; __syncthreads();
    for (int s = 32; s > 0; s >>= 1) { if (t < s) red[t] = fmaxf(red[t], red[t+s]); __syncthreads(); }
    float mx = red[0]; __syncthreads();
    float e = (t < CC) ? __expf(g - mx) : 0.f;
    red[t] = e; __syncthreads();
    for (int s = 32; s > 0; s >>= 1) { if (t < s) red[t] += red[t+s]; __syncthreads(); }
    if (t < CC) g_Fatt[(b*CC+d1)*CC + t] = e/red[0];
}

// ---------------- frequency apply ----------------
__global__ __launch_bounds__(256) void k_fapply() {
    __shared__ float att[CC*CC];
    int tid = threadIdx.x;
    int b = blockIdx.y;
    for (int i = tid; i < CC*CC; i += 256) {
        int d2 = i/CC, d1 = i%CC;
        att[i] = g_Fatt[b*CC*CC + d1*CC + d2];
    }
    __syncthreads();
    size_t i = (size_t)blockIdx.x*256 + tid;
    const float* v = g_fqkv + (size_t)b*TD*NHW + (size_t)120*NHW + i;
    float acc[CC] = {};
    for (int d2 = 0; d2 < CC; d2++) {
        float vv = v[(size_t)d2*NHW];
        #pragma unroll
        for (int d1 = 0; d1 < CC; d1++) acc[d1] += att[d2*CC+d1]*vv;
    }
    float* o = g_cat + (size_t)b*4500*HW + (size_t)120*NHW + i;
    #pragma unroll
    for (int d1 = 0; d1 < CC; d1++) o[(size_t)d1*NHW] = acc[d1];
}

// ---------------- fused LayerNorm + MLP + residual ----------------
__global__ __launch_bounds__(256) void k_lnmlp(const float* __restrict__ x,
                                               const float* __restrict__ gamma,
                                               const float* __restrict__ beta,
                                               const float* __restrict__ w1,
                                               const float* __restrict__ w2,
                                               float* __restrict__ out) {
    extern __shared__ float dynsm[];
    float* W1s = dynsm;
    float* W2s = W1s + TD*CC;
    float* gs  = W2s + CC*CC;
    float* bs  = gs + TD;
    int tid = threadIdx.x;
    for (int idx = tid; idx < TD*CC; idx += 256) {
        int dd = idx % CC, ch = idx / CC;
        W1s[idx] = w1[dd*TD + ch];
    }
    for (int idx = tid; idx < CC*CC; idx += 256) W2s[idx] = w2[idx];
    for (int idx = tid; idx < TD; idx += 256) { gs[idx] = gamma[idx]; bs[idx] = beta[idx]; }
    __syncthreads();
    int b = blockIdx.y;
    size_t i = (size_t)blockIdx.x*256 + tid;
    const float* cp = g_cat + (size_t)b*4500*HW + i;
    float s = 0.f, ss = 0.f;
    for (int ch = 0; ch < TD; ch++) { float v = cp[(size_t)ch*NHW]; s += v; ss += v*v; }
    float mu = s * (1.f/TD);
    float var = ss * (1.f/TD) - mu*mu;
    float inv = rsqrtf(var + 1e-5f);
    float hv[CC] = {};
    for (int ch = 0; ch < TD; ch++) {
        float v = (cp[(size_t)ch*NHW] - mu)*inv*gs[ch] + bs[ch];
        #pragma unroll
        for (int dd = 0; dd < CC; dd++) hv[dd] += W1s[ch*CC + dd]*v;
    }
    #pragma unroll
    for (int dd = 0; dd < CC; dd++) hv[dd] = fmaxf(hv[dd], 0.f);
    const float* xb = x + (size_t)b*CC*NHW;
    float* ob = out + (size_t)b*CC*NHW;
    for (int c = 0; c < CC; c++) {
        float acc = 0.f;
        #pragma unroll
        for (int h = 0; h < CC; h++) acc += W2s[c*CC + h]*hv[h];
        ob[(size_t)c*NHW + i] = acc + xb[(size_t)c*NHW + i];
    }
}

// ---------------- launch ----------------
extern "C" void kernel_launch(void* const* d_in, const int* in_sizes, int n_in,
                              void* d_out, int out_size) {
    const float* x    = (const float*)d_in[0];
    const float* wsq  = (const float*)d_in[1];
    const float* wskv = (const float*)d_in[2];
    const float* waq  = (const float*)d_in[3];
    const float* wfq  = (const float*)d_in[4];
    const float* gam  = (const float*)d_in[5];
    const float* bet  = (const float*)d_in[6];
    const float* w1   = (const float*)d_in[7];
    const float* w2   = (const float*)d_in[8];
    float* out = (float*)d_out;

    cudaFuncSetAttribute(k_lnmlp, cudaFuncAttributeMaxDynamicSharedMemorySize, 59040);

    k_zero    <<<57, 256>>>();
    k_proj_sq <<<dim3(36,100), 256>>>(x, wsq);
    k_proj_skv<<<dim3(9,100),  256>>>(x, wskv);
    k_proj180 <<<dim3(36,100), 256>>>(x, waq, 0);
    k_proj180 <<<dim3(36,100), 256>>>(x, wfq, 1);
    k_rq      <<<dim3(36,BN),  256>>>();
    k_rk      <<<dim3(9,BN),   256>>>();
    k_gemm1   <<<dim3(18,72,BN), 256>>>();
    k_softmax <<<dim3(HW,BN),  256>>>();
    k_gemm2   <<<dim3(72,12,BN), 256>>>();
    k_anorm   <<<BN*NA, 256>>>();
    k_agram   <<<BN*CC, 256>>>();
    k_asoft   <<<BN*NA, 32>>>();
    k_aapply  <<<dim3(36,CC,BN), 256>>>();
    k_fnorm   <<<BN*CC, 256>>>();
    k_fgram   <<<dim3(100,BN), 256>>>();
    k_fsoft   <<<BN*CC, 64>>>();
    k_fapply  <<<dim3(900,BN), 256>>>();
    k_lnmlp   <<<dim3(900,BN), 256, 59040>>>(x, gam, bet, w1, w2, out);
}